// round 13
// baseline (speedup 1.0000x reference)
#include <cuda_runtime.h>
#include <cuda_bf16.h>
#include <math.h>
#include <stdint.h>

// ---------------- problem constants ----------------
#define TOKENS      4096
#define HID         1024
#define NEXP        8
#define CAP         1536
#define NSLOTS      8192
#define DISP_ELEMS  50331648L
#define ZERO_ELEMS  100663296L
#define PROBS_OFF   100663296L
#define AUX_OFF     100696064L

// zero-fill split: k_prep covers chunks [0,64), k_gemm covers [64,384). chunk = 65536 uint4 = 1 MB
#define PREP_ZCHUNKS   64L
#define PREP_ZUINT4    (PREP_ZCHUNKS * 65536L)     // 4194304
#define PREP_THREADS   163840L                     // 640 blocks * 256

// ---------------- device scratch ----------------
__device__ __align__(128) __nv_bfloat16 g_Ahb[TOKENS * HID];
__device__ __align__(128) __nv_bfloat16 g_Alb[TOKENS * HID];
__device__ __align__(128) __nv_bfloat16 g_Bhb[HID * HID];   // w1^T: [n][k]
__device__ __align__(128) __nv_bfloat16 g_Blb[HID * HID];
__device__ __align__(128) float g_plog[4 * TOKENS * NEXP];  // partial logits (4 N-slices)
__device__ __align__(128) float g_avgp[512 * 1024];
__device__ float g_adj[16];
__device__ float g_psum[32 * 8];
__device__ int   g_cnt[32 * 8];
__device__ int   g_done  = 0;
__device__ int   g_done2 = 0;

// ---------------- PTX helpers (portable: sm_80+) ----------------
__device__ __forceinline__ uint32_t smem_u32(const void* p) {
    uint32_t a;
    asm("{ .reg .u64 t; cvta.to.shared.u64 t, %1; cvt.u32.u64 %0, t; }" : "=r"(a) : "l"(p));
    return a;
}

#define CP16(dst_u32, src_ptr) \
    asm volatile("cp.async.cg.shared.global [%0], [%1], 16;" :: "r"(dst_u32), "l"(src_ptr))
#define CP_COMMIT() asm volatile("cp.async.commit_group;" ::: "memory")
#define CP_WAIT1()  asm volatile("cp.async.wait_group 1;" ::: "memory")
#define CP_WAIT0()  asm volatile("cp.async.wait_group 0;" ::: "memory")

#define LDSM4(R, addr) \
    asm volatile("ldmatrix.sync.aligned.m8n8.x4.shared.b16 {%0,%1,%2,%3}, [%4];" \
        : "=r"((R)[0]), "=r"((R)[1]), "=r"((R)[2]), "=r"((R)[3]) : "r"(addr))

#define MMA16816(acc4, a4, b0, b1) \
    asm volatile("mma.sync.aligned.m16n8k16.row.col.f32.bf16.bf16.f32 " \
        "{%0,%1,%2,%3},{%4,%5,%6,%7},{%8,%9},{%0,%1,%2,%3};" \
        : "+f"((acc4)[0]), "+f"((acc4)[1]), "+f"((acc4)[2]), "+f"((acc4)[3]) \
        : "r"((a4)[0]), "r"((a4)[1]), "r"((a4)[2]), "r"((a4)[3]), "r"(b0), "r"(b1))

__device__ __forceinline__ uint32_t pack_bf2(float a, float b) {
    __nv_bfloat162 t = __floats2bfloat162_rn(a, b);
    return *(uint32_t*)&t;
}

// ============ k_prep: zero-fill head + split A (512 blks) + split w1 (128 blks) ============
__global__ void k_prep(const float* __restrict__ hs, const float* __restrict__ w1,
                       float* __restrict__ out)
{
    const int tid = threadIdx.x;

    // ---- fire-and-forget zero-fill of the first 64 MB (drains under the work below) ----
    {
        uint4 zv; zv.x = zv.y = zv.z = zv.w = 0u;
        uint4* zp = (uint4*)out;
        long g = (long)blockIdx.x * 256 + tid;
        #pragma unroll 4
        for (long i = g; i < PREP_ZUINT4; i += PREP_THREADS)
            __stcs(zp + i, zv);
    }

    if (blockIdx.x >= 512) {
        // ---- w1 transpose + hi/lo split: 128 blocks = 32 N-strips x 4 K-quarters ----
        __shared__ float t[32][33];
        const int idx = blockIdx.x - 512;
        const int nb = (idx >> 2) * 32;
        const int kt0 = (idx & 3) * 8;
        const int tx = tid & 31, ty = tid >> 5;   // 32 x 8
        for (int kt = kt0; kt < kt0 + 8; kt++) {
            const int kb = kt * 32;
            #pragma unroll
            for (int j = 0; j < 4; j++) {
                int kk = ty + j * 8;
                t[kk][tx] = w1[(long)(kb + kk) * 1024 + nb + tx];
            }
            __syncthreads();
            #pragma unroll
            for (int j = 0; j < 4; j++) {
                int nn = ty + j * 8;
                float x = t[tx][nn];
                __nv_bfloat16 h = __float2bfloat16_rn(x);
                float hf = __bfloat162float(h);
                long o = (long)(nb + nn) * 1024 + kb + tx;
                g_Bhb[o] = h;
                g_Blb[o] = __float2bfloat16_rn(x - hf);
            }
            __syncthreads();
        }
        return;
    }
    const int blk = blockIdx.x;      // 8 tokens each
    const float4* in = (const float4*)(hs + (long)blk * 8 * 1024) + tid;
    uint2* ah = ((uint2*)g_Ahb) + (long)blk * 8 * 256 + tid;
    uint2* al = ((uint2*)g_Alb) + (long)blk * 8 * 256 + tid;
    float4 s = make_float4(0.f, 0.f, 0.f, 0.f);
    #pragma unroll
    for (int t = 0; t < 8; t++) {
        float4 x = in[(long)t * 256];
        s.x += x.x; s.y += x.y; s.z += x.z; s.w += x.w;
        float h0 = __bfloat162float(__float2bfloat16_rn(x.x));
        float h1 = __bfloat162float(__float2bfloat16_rn(x.y));
        float h2 = __bfloat162float(__float2bfloat16_rn(x.z));
        float h3 = __bfloat162float(__float2bfloat16_rn(x.w));
        uint2 ph, pl;
        ph.x = pack_bf2(h0, h1);             ph.y = pack_bf2(h2, h3);
        pl.x = pack_bf2(x.x - h0, x.y - h1); pl.y = pack_bf2(x.z - h2, x.w - h3);
        ah[(long)t * 256] = ph;
        al[(long)t * 256] = pl;
    }
    ((float4*)(g_avgp + (long)blk * 1024))[tid] = s;
}

// ============ big kernel: 128x256 tile, 512 threads (16 warps, 4m x 4n) ============
#define OFF_BIAS 0
#define OFF_W2   1024
#define OFF_STG  9216
#define ALO      10240
#define B_OFF    20480
#define BLO      20480
#define STAGE    61440
#define DYNSMEM  (OFF_STG + 3 * STAGE)   // 193536

__device__ __forceinline__ void load_stage(uint32_t stg, int tid, int m0, int n0, int k0)
{
    {
        int r = tid >> 2, c = tid & 3;
        uint32_t da = stg + r * 80 + c * 16;
        CP16(da,       g_Ahb + (long)(m0 + r) * 1024 + k0 + c * 8);
        CP16(da + ALO, g_Alb + (long)(m0 + r) * 1024 + k0 + c * 8);
    }
    #pragma unroll
    for (int j = 0; j < 2; j++) {
        int idx = tid + j * 512;
        int r = idx >> 2, c = idx & 3;
        uint32_t db = stg + B_OFF + r * 80 + c * 16;
        CP16(db,       g_Bhb + (long)(n0 + r) * 1024 + k0 + c * 8);
        CP16(db + BLO, g_Blb + (long)(n0 + r) * 1024 + k0 + c * 8);
    }
}

__global__ __launch_bounds__(512, 1)
void k_gemm(const float* __restrict__ b1, const float* __restrict__ w2,
            const float* __restrict__ wc1, const float* __restrict__ bc1,
            const float* __restrict__ wc2, const float* __restrict__ bc2,
            const float* __restrict__ cache, float* __restrict__ out)
{
    extern __shared__ char smraw[];
    const uint32_t sb = smem_u32(smraw);
    const int tid = threadIdx.x;
    const int warp = tid >> 5;
    const int lane = tid & 31;

    // ---------- side CTAs: cache-MLP path ----------
    if (blockIdx.x >= 128) {
        const int b = blockIdx.x - 128;
        float* comb = (float*)smraw;
        float* hcS  = (float*)(smraw + 4224);
        if (tid < 256) {
            float4 s = make_float4(0.f, 0.f, 0.f, 0.f);
            const float4* ap = (const float4*)(g_avgp + (long)b * 256 * 1024) + tid;
            #pragma unroll 8
            for (int c = 0; c < 256; c++) {
                float4 v = ap[(long)c * 256];
                s.x += v.x; s.y += v.y; s.z += v.z; s.w += v.w;
            }
            const float inv = 1.f / 2048.f;
            ((float4*)comb)[tid] = make_float4(s.x * inv, s.y * inv, s.z * inv, s.w * inv);
            if (tid < 8) comb[1024 + tid] = cache[tid];
        }
        __syncthreads();
        {
            int j = tid * 2;
            float2 acc = *(const float2*)(bc1 + j);
            const float2* wp = (const float2*)(wc1 + j);
            for (int i = 0; i < 1032; i++) {
                float cv = comb[i];
                float2 w = wp[(long)i * 512];
                acc.x = fmaf(cv, w.x, acc.x);
                acc.y = fmaf(cv, w.y, acc.y);
            }
            hcS[j]     = fmaxf(acc.x, 0.f);
            hcS[j + 1] = fmaxf(acc.y, 0.f);
        }
        __syncthreads();
        if (warp < 8) {
            float acc = 0.f;
            for (int i = lane; i < 1024; i += 32)
                acc = fmaf(hcS[i], wc2[i * 8 + warp], acc);
            #pragma unroll
            for (int off = 16; off > 0; off >>= 1)
                acc += __shfl_down_sync(0xffffffffu, acc, off);
            if (lane == 0) g_adj[b * 8 + warp] = tanhf(acc + bc2[warp]);
        }
        return;
    }

    // ---------- GEMM CTAs ----------
    const int wm = warp >> 2;
    const int wn = warp & 3;
    const int gg = lane >> 2;
    const int tt = lane & 3;
    const int blockN = blockIdx.x & 3;
    const int blockM = blockIdx.x >> 2;
    const int m0 = blockM * 128;
    const int n0 = blockN * 256;

    float* sBias = (float*)(smraw + OFF_BIAS);
    float* sW2   = (float*)(smraw + OFF_W2);
    if (tid < 256) sBias[tid] = b1[n0 + tid];
    ((float4*)sW2)[tid] = ((const float4*)(w2 + (long)n0 * 8))[tid];

    const uint32_t aRowOff = (uint32_t)((wm * 32 + (lane & 15)) * 80) + ((lane >> 4) << 4);
    const uint32_t bRowOff = (uint32_t)((wn * 64 + (lane & 7) + ((lane & 16) >> 1)) * 80)
                             + ((lane & 8) << 1);

    float acc[2][8][4];
    #pragma unroll
    for (int f = 0; f < 2; f++)
        #pragma unroll
        for (int n = 0; n < 8; n++)
            #pragma unroll
            for (int q = 0; q < 4; q++) acc[f][n][q] = 0.f;

    load_stage(sb + OFF_STG,         tid, m0, n0, 0);
    CP_COMMIT();
    load_stage(sb + OFF_STG + STAGE, tid, m0, n0, 32);
    CP_COMMIT();

    uint4* zp = (uint4*)out;
    uint4 zv; zv.x = zv.y = zv.z = zv.w = 0u;
    const long zg = (long)blockIdx.x * 512 + tid;

    for (int kt = 0; kt < 32; kt++) {
        const int slot = kt % 3;
        const uint32_t stgA = sb + OFF_STG + slot * STAGE;
        const uint32_t stgB = stgA + B_OFF;

        if (kt < 31) { CP_WAIT1(); } else { CP_WAIT0(); }
        __syncthreads();

        if (kt < 30) {
            load_stage(sb + OFF_STG + ((kt + 2) % 3) * STAGE, tid, m0, n0, (kt + 2) * 32);
            CP_COMMIT();
        }

        #pragma unroll
        for (int sub = 0; sub < 2; sub++) {
            uint32_t ah[2][4], al[2][4];
            #pragma unroll
            for (int f = 0; f < 2; f++) {
                uint32_t aa = stgA + aRowOff + f * 1280 + sub * 32;
                LDSM4(ah[f], aa);
                LDSM4(al[f], aa + ALO);
            }
            #pragma unroll
            for (int np = 0; np < 4; np++) {
                uint32_t ba = stgB + bRowOff + np * 1280 + sub * 32;
                uint32_t bh[4], bl[4];
                LDSM4(bh, ba);
                LDSM4(bl, ba + BLO);
                #pragma unroll
                for (int f = 0; f < 2; f++) {
                    MMA16816(acc[f][2 * np],     ah[f], bh[0], bh[1]);
                    MMA16816(acc[f][2 * np],     ah[f], bl[0], bl[1]);
                    MMA16816(acc[f][2 * np],     al[f], bh[0], bh[1]);
                    MMA16816(acc[f][2 * np + 1], ah[f], bh[2], bh[3]);
                    MMA16816(acc[f][2 * np + 1], ah[f], bl[2], bl[3]);
                    MMA16816(acc[f][2 * np + 1], al[f], bh[2], bh[3]);
                }
            }
            // zero-fill chunks [64, 384): 10 per kt, 5 per sub-step
            #pragma unroll 5
            for (int j = 0; j < 5; j++)
                __stcs(zp + (PREP_ZCHUNKS + (long)(kt * 10 + sub * 5 + j)) * 65536 + zg, zv);
        }
    }

    // ---------- epilogue ----------
    float* sPart = (float*)(smraw + OFF_STG);
    #pragma unroll
    for (int f = 0; f < 2; f++) {
        float le0[8] = {0,0,0,0,0,0,0,0};
        float le1[8] = {0,0,0,0,0,0,0,0};
        #pragma unroll
        for (int nf = 0; nf < 8; nf++) {
            int cb = wn * 64 + nf * 8 + tt * 2;
            float bv0 = sBias[cb], bv1 = sBias[cb + 1];
            float h00 = fmaxf(acc[f][nf][0] + bv0, 0.f);
            float h01 = fmaxf(acc[f][nf][1] + bv1, 0.f);
            float h10 = fmaxf(acc[f][nf][2] + bv0, 0.f);
            float h11 = fmaxf(acc[f][nf][3] + bv1, 0.f);
            const float* w0 = &sW2[cb * 8];
            const float* w1p = &sW2[(cb + 1) * 8];
            #pragma unroll
            for (int e = 0; e < 8; e++) {
                le0[e] += h00 * w0[e] + h01 * w1p[e];
                le1[e] += h10 * w0[e] + h11 * w1p[e];
            }
        }
        #pragma unroll
        for (int e = 0; e < 8; e++) {
            le0[e] += __shfl_xor_sync(0xffffffffu, le0[e], 1);
            le0[e] += __shfl_xor_sync(0xffffffffu, le0[e], 2);
            le1[e] += __shfl_xor_sync(0xffffffffu, le1[e], 1);
            le1[e] += __shfl_xor_sync(0xffffffffu, le1[e], 2);
        }
        if (tt == 0) {
            int r0 = wm * 32 + f * 16 + gg;
            float* p0 = &sPart[(wn * 128 + r0) * 8];
            *(float4*)p0       = make_float4(le0[0], le0[1], le0[2], le0[3]);
            *(float4*)(p0 + 4) = make_float4(le0[4], le0[5], le0[6], le0[7]);
            float* p1 = &sPart[(wn * 128 + r0 + 8) * 8];
            *(float4*)p1       = make_float4(le1[0], le1[1], le1[2], le1[3]);
            *(float4*)(p1 + 4) = make_float4(le1[4], le1[5], le1[6], le1[7]);
        }
    }
    __syncthreads();
    if (tid < 256) {
        int row = tid >> 1, e4 = (tid & 1) * 4;
        float4 v0 = *(float4*)&sPart[(0 * 128 + row) * 8 + e4];
        float4 v1 = *(float4*)&sPart[(1 * 128 + row) * 8 + e4];
        float4 v2 = *(float4*)&sPart[(2 * 128 + row) * 8 + e4];
        float4 v3 = *(float4*)&sPart[(3 * 128 + row) * 8 + e4];
        float4 v = make_float4(((v0.x + v1.x) + v2.x) + v3.x,
                               ((v0.y + v1.y) + v2.y) + v3.y,
                               ((v0.z + v1.z) + v2.z) + v3.z,
                               ((v0.w + v1.w) + v2.w) + v3.w);
        *(float4*)(g_plog + ((long)blockN * 4096 + m0 + row) * 8 + e4) = v;
    }
}

// ============ k_tail: softmax/top2 + counts, 32-block sync, positions + scatter + aux ============
__global__ void k_tail(const float* __restrict__ b2, float* __restrict__ out)
{
    __shared__ float wsum[4][8];
    __shared__ int scnt[8];
    __shared__ int sE[256];
    __shared__ float sP[256];
    __shared__ unsigned int wtot[8][4];
    __shared__ int base[8];

    const int b = blockIdx.x;
    const int tid = threadIdx.x;
    const int lane = tid & 31, warp = tid >> 5;

    if (tid < 8) scnt[tid] = 0;
    __syncthreads();

    if (tid < 128) {
        int tok = b * 128 + tid;
        int bb = tok >> 11;
        float l[8] = {0,0,0,0,0,0,0,0};
        #pragma unroll
        for (int q = 0; q < 4; q++) {
            const float4* p = (const float4*)(g_plog + ((long)q * 4096 + tok) * 8);
            float4 u = p[0], v = p[1];
            l[0] += u.x; l[1] += u.y; l[2] += u.z; l[3] += u.w;
            l[4] += v.x; l[5] += v.y; l[6] += v.z; l[7] += v.w;
        }
        float m = -1e30f;
        #pragma unroll
        for (int e = 0; e < 8; e++) {
            l[e] += b2[e] + g_adj[bb * 8 + e];
            m = fmaxf(m, l[e]);
        }
        float p[8], s = 0.f;
        #pragma unroll
        for (int e = 0; e < 8; e++) { p[e] = expf(l[e] - m); s += p[e]; }
        float inv = 1.f / s;
        #pragma unroll
        for (int e = 0; e < 8; e++) p[e] *= inv;
        {
            float* pr = out + PROBS_OFF + (long)tok * 8;
            *(float4*)pr       = make_float4(p[0], p[1], p[2], p[3]);
            *(float4*)(pr + 4) = make_float4(p[4], p[5], p[6], p[7]);
        }
        int e1 = 0;
        #pragma unroll
        for (int e = 1; e < 8; e++) if (p[e] > p[e1]) e1 = e;
        int e2 = (e1 == 0) ? 1 : 0;
        #pragma unroll
        for (int e = 0; e < 8; e++) if (e != e1 && p[e] > p[e2]) e2 = e;
        float d = p[e1] + p[e2] + 1e-8f;
        sE[tid * 2]     = e1;
        sE[tid * 2 + 1] = e2;
        sP[tid * 2]     = p[e1] / d;
        sP[tid * 2 + 1] = p[e2] / d;
        atomicAdd(&scnt[e1], 1);
        atomicAdd(&scnt[e2], 1);

        float w[8];
        #pragma unroll
        for (int e = 0; e < 8; e++) {
            float v = p[e];
            #pragma unroll
            for (int off = 16; off > 0; off >>= 1)
                v += __shfl_xor_sync(0xffffffffu, v, off);
            w[e] = v;
        }
        if (lane == 0) {
            #pragma unroll
            for (int e = 0; e < 8; e++) wsum[warp][e] = w[e];
        }
    }
    __syncthreads();
    if (tid < 8) {
        g_psum[b * 8 + tid] =
            ((wsum[0][tid] + wsum[1][tid]) + wsum[2][tid]) + wsum[3][tid];
        g_cnt[b * 8 + tid] = scnt[tid];
    }
    __threadfence();
    __syncthreads();

    if (tid == 0) {
        atomicAdd(&g_done, 1);
        while (atomicAdd(&g_done, 0) < 32) __nanosleep(64);
    }
    __syncthreads();
    __threadfence();

    if (tid < 8) {
        int s = 0;
        for (int q = 0; q < b; q++) s += g_cnt[q * 8 + tid];
        base[tid] = s;
    }

    const int e = sE[tid];
    const float pv = sP[tid];
    unsigned int c[4] = {0, 0, 0, 0};
    c[e >> 1] = 1u << ((e & 1) * 16);
    unsigned int inc[4] = {c[0], c[1], c[2], c[3]};
    #pragma unroll
    for (int off = 1; off < 32; off <<= 1) {
        #pragma unroll
        for (int w = 0; w < 4; w++) {
            unsigned int v = __shfl_up_sync(0xffffffffu, inc[w], off);
            if (lane >= off) inc[w] += v;
        }
    }
    if (lane == 31) {
        #pragma unroll
        for (int w = 0; w < 4; w++) wtot[warp][w] = inc[w];
    }
    __syncthreads();

    unsigned int exc = inc[e >> 1] - c[e >> 1];
    for (int q = 0; q < warp; q++) exc += wtot[q][e >> 1];
    int local = (int)((exc >> ((e & 1) * 16)) & 0xffffu);
    int pos = base[e] + local;

    if (pos < CAP) {
        long n = (long)b * 256 + tid;
        long tok = n >> 1;
        long o = tok * 12288L + (long)e * 1536L + pos;
        out[o] = 1.0f;
        out[DISP_ELEMS + o] = pv;
    }

    if (b == 0 && tid == 0) {
        float aux = 0.f;
        #pragma unroll
        for (int ee = 0; ee < 8; ee++) {
            float ps = 0.f; int ct = 0;
            for (int q = 0; q < 32; q++) {
                ps += g_psum[q * 8 + ee];
                ct += g_cnt[q * 8 + ee];
            }
            aux += (ps * (1.f / 4096.f)) * ((float)ct * (1.f / 8192.f));
        }
        out[AUX_OFF] = aux * 8.f;
    }

    if (tid == 0) {
        int v = atomicAdd(&g_done2, 1);
        if (v == 31) { g_done = 0; g_done2 = 0; }
    }
}

// ---------------- launch ----------------
extern "C" void kernel_launch(void* const* d_in, const int* in_sizes, int n_in,
                              void* d_out, int out_size)
{
    const float* hs    = (const float*)d_in[0];
    const float* w1    = (const float*)d_in[1];
    const float* b1    = (const float*)d_in[2];
    const float* w2    = (const float*)d_in[3];
    const float* b2    = (const float*)d_in[4];
    const float* wc1   = (const float*)d_in[5];
    const float* bc1   = (const float*)d_in[6];
    const float* wc2   = (const float*)d_in[7];
    const float* bc2   = (const float*)d_in[8];
    const float* cache = (const float*)d_in[9];
    float* out = (float*)d_out;

    cudaFuncSetAttribute(k_gemm, cudaFuncAttributeMaxDynamicSharedMemorySize, DYNSMEM);

    k_prep<<<640, 256>>>(hs, w1, out);
    k_gemm<<<130, 512, DYNSMEM>>>(b1, w2, wc1, bc1, wc2, bc2, cache, out);
    k_tail<<<32, 256>>>(b2, out);
}

// round 14
// speedup vs baseline: 1.2456x; 1.2456x over previous
#include <cuda_runtime.h>
#include <cuda_bf16.h>
#include <math.h>
#include <stdint.h>

// ---------------- problem constants ----------------
#define TOKENS      4096
#define HID         1024
#define NEXP        8
#define CAP         1536
#define NSLOTS      8192
#define DISP_ELEMS  50331648L
#define ZERO_ELEMS  100663296L
#define PROBS_OFF   100663296L
#define AUX_OFF     100696064L

// ---------------- device scratch ----------------
__device__ __align__(128) __nv_bfloat16 g_Ahb[TOKENS * HID];
__device__ __align__(128) __nv_bfloat16 g_Alb[TOKENS * HID];
__device__ __align__(128) __nv_bfloat16 g_Bhb[HID * HID];   // w1^T: [n][k]
__device__ __align__(128) __nv_bfloat16 g_Blb[HID * HID];
__device__ __align__(128) float g_plog[4 * TOKENS * NEXP];  // partial logits (4 N-slices)
__device__ __align__(128) float g_avgp[512 * 1024];
__device__ float g_adj[16];
__device__ float g_psum[32 * 8];
__device__ int   g_cnt[32 * 8];
__device__ int   g_done  = 0;
__device__ int   g_done2 = 0;

// ---------------- PTX helpers (portable: sm_80+) ----------------
__device__ __forceinline__ uint32_t smem_u32(const void* p) {
    uint32_t a;
    asm("{ .reg .u64 t; cvta.to.shared.u64 t, %1; cvt.u32.u64 %0, t; }" : "=r"(a) : "l"(p));
    return a;
}

#define CP16(dst_u32, src_ptr) \
    asm volatile("cp.async.cg.shared.global [%0], [%1], 16;" :: "r"(dst_u32), "l"(src_ptr))
#define CP_COMMIT() asm volatile("cp.async.commit_group;" ::: "memory")
#define CP_WAIT1()  asm volatile("cp.async.wait_group 1;" ::: "memory")
#define CP_WAIT0()  asm volatile("cp.async.wait_group 0;" ::: "memory")

#define LDSM4(R, addr) \
    asm volatile("ldmatrix.sync.aligned.m8n8.x4.shared.b16 {%0,%1,%2,%3}, [%4];" \
        : "=r"((R)[0]), "=r"((R)[1]), "=r"((R)[2]), "=r"((R)[3]) : "r"(addr))

#define MMA16816(acc4, a4, b0, b1) \
    asm volatile("mma.sync.aligned.m16n8k16.row.col.f32.bf16.bf16.f32 " \
        "{%0,%1,%2,%3},{%4,%5,%6,%7},{%8,%9},{%0,%1,%2,%3};" \
        : "+f"((acc4)[0]), "+f"((acc4)[1]), "+f"((acc4)[2]), "+f"((acc4)[3]) \
        : "r"((a4)[0]), "r"((a4)[1]), "r"((a4)[2]), "r"((a4)[3]), "r"(b0), "r"(b1))

__device__ __forceinline__ uint32_t pack_bf2(float a, float b) {
    __nv_bfloat162 t = __floats2bfloat162_rn(a, b);
    return *(uint32_t*)&t;
}

// ============ k_prep: blocks 0-511 split A (8 tokens each); 512-639 split w1 ============
__global__ void k_prep(const float* __restrict__ hs, const float* __restrict__ w1)
{
    const int tid = threadIdx.x;
    if (blockIdx.x >= 512) {
        // ---- w1 transpose + hi/lo split: 128 blocks = 32 N-strips x 4 K-quarters ----
        __shared__ float t[32][33];
        const int idx = blockIdx.x - 512;
        const int nb = (idx >> 2) * 32;
        const int kt0 = (idx & 3) * 8;
        const int tx = tid & 31, ty = tid >> 5;   // 32 x 8
        for (int kt = kt0; kt < kt0 + 8; kt++) {
            const int kb = kt * 32;
            #pragma unroll
            for (int j = 0; j < 4; j++) {
                int kk = ty + j * 8;
                t[kk][tx] = w1[(long)(kb + kk) * 1024 + nb + tx];
            }
            __syncthreads();
            #pragma unroll
            for (int j = 0; j < 4; j++) {
                int nn = ty + j * 8;
                float x = t[tx][nn];
                __nv_bfloat16 h = __float2bfloat16_rn(x);
                float hf = __bfloat162float(h);
                long o = (long)(nb + nn) * 1024 + kb + tx;
                g_Bhb[o] = h;
                g_Blb[o] = __float2bfloat16_rn(x - hf);
            }
            __syncthreads();
        }
        return;
    }
    const int blk = blockIdx.x;      // 8 tokens each
    const float4* in = (const float4*)(hs + (long)blk * 8 * 1024) + tid;
    uint2* ah = ((uint2*)g_Ahb) + (long)blk * 8 * 256 + tid;
    uint2* al = ((uint2*)g_Alb) + (long)blk * 8 * 256 + tid;
    float4 s = make_float4(0.f, 0.f, 0.f, 0.f);
    #pragma unroll
    for (int t = 0; t < 8; t++) {
        float4 x = in[(long)t * 256];
        s.x += x.x; s.y += x.y; s.z += x.z; s.w += x.w;
        float h0 = __bfloat162float(__float2bfloat16_rn(x.x));
        float h1 = __bfloat162float(__float2bfloat16_rn(x.y));
        float h2 = __bfloat162float(__float2bfloat16_rn(x.z));
        float h3 = __bfloat162float(__float2bfloat16_rn(x.w));
        uint2 ph, pl;
        ph.x = pack_bf2(h0, h1);             ph.y = pack_bf2(h2, h3);
        pl.x = pack_bf2(x.x - h0, x.y - h1); pl.y = pack_bf2(x.z - h2, x.w - h3);
        ah[(long)t * 256] = ph;
        al[(long)t * 256] = pl;
    }
    ((float4*)(g_avgp + (long)blk * 1024))[tid] = s;
}

// ============ big kernel: 128x256 tile, 512 threads (16 warps, 4m x 4n) ============
#define OFF_BIAS 0
#define OFF_W2   1024
#define OFF_STG  9216
#define ALO      10240
#define B_OFF    20480
#define BLO      20480
#define STAGE    61440
#define DYNSMEM  (OFF_STG + 3 * STAGE)   // 193536

__device__ __forceinline__ void load_stage(uint32_t stg, int tid, int m0, int n0, int k0)
{
    {
        int r = tid >> 2, c = tid & 3;
        uint32_t da = stg + r * 80 + c * 16;
        CP16(da,       g_Ahb + (long)(m0 + r) * 1024 + k0 + c * 8);
        CP16(da + ALO, g_Alb + (long)(m0 + r) * 1024 + k0 + c * 8);
    }
    #pragma unroll
    for (int j = 0; j < 2; j++) {
        int idx = tid + j * 512;
        int r = idx >> 2, c = idx & 3;
        uint32_t db = stg + B_OFF + r * 80 + c * 16;
        CP16(db,       g_Bhb + (long)(n0 + r) * 1024 + k0 + c * 8);
        CP16(db + BLO, g_Blb + (long)(n0 + r) * 1024 + k0 + c * 8);
    }
}

__global__ __launch_bounds__(512, 1)
void k_gemm(const float* __restrict__ b1, const float* __restrict__ w2,
            const float* __restrict__ wc1, const float* __restrict__ bc1,
            const float* __restrict__ wc2, const float* __restrict__ bc2,
            const float* __restrict__ cache, float* __restrict__ out)
{
    extern __shared__ char smraw[];
    const uint32_t sb = smem_u32(smraw);
    const int tid = threadIdx.x;
    const int warp = tid >> 5;
    const int lane = tid & 31;

    // ---------- side CTAs: cache-MLP path ----------
    if (blockIdx.x >= 128) {
        const int b = blockIdx.x - 128;
        float* comb = (float*)smraw;
        float* hcS  = (float*)(smraw + 4224);
        if (tid < 256) {
            float4 s = make_float4(0.f, 0.f, 0.f, 0.f);
            const float4* ap = (const float4*)(g_avgp + (long)b * 256 * 1024) + tid;
            #pragma unroll 8
            for (int c = 0; c < 256; c++) {
                float4 v = ap[(long)c * 256];
                s.x += v.x; s.y += v.y; s.z += v.z; s.w += v.w;
            }
            const float inv = 1.f / 2048.f;
            ((float4*)comb)[tid] = make_float4(s.x * inv, s.y * inv, s.z * inv, s.w * inv);
            if (tid < 8) comb[1024 + tid] = cache[tid];
        }
        __syncthreads();
        {
            int j = tid * 2;
            float2 acc = *(const float2*)(bc1 + j);
            const float2* wp = (const float2*)(wc1 + j);
            for (int i = 0; i < 1032; i++) {
                float cv = comb[i];
                float2 w = wp[(long)i * 512];
                acc.x = fmaf(cv, w.x, acc.x);
                acc.y = fmaf(cv, w.y, acc.y);
            }
            hcS[j]     = fmaxf(acc.x, 0.f);
            hcS[j + 1] = fmaxf(acc.y, 0.f);
        }
        __syncthreads();
        if (warp < 8) {
            float acc = 0.f;
            for (int i = lane; i < 1024; i += 32)
                acc = fmaf(hcS[i], wc2[i * 8 + warp], acc);
            #pragma unroll
            for (int off = 16; off > 0; off >>= 1)
                acc += __shfl_down_sync(0xffffffffu, acc, off);
            if (lane == 0) g_adj[b * 8 + warp] = tanhf(acc + bc2[warp]);
        }
        return;
    }

    // ---------- GEMM CTAs ----------
    const int wm = warp >> 2;
    const int wn = warp & 3;
    const int gg = lane >> 2;
    const int tt = lane & 3;
    const int blockN = blockIdx.x & 3;
    const int blockM = blockIdx.x >> 2;
    const int m0 = blockM * 128;
    const int n0 = blockN * 256;

    float* sBias = (float*)(smraw + OFF_BIAS);
    float* sW2   = (float*)(smraw + OFF_W2);
    if (tid < 256) sBias[tid] = b1[n0 + tid];
    ((float4*)sW2)[tid] = ((const float4*)(w2 + (long)n0 * 8))[tid];

    const uint32_t aRowOff = (uint32_t)((wm * 32 + (lane & 15)) * 80) + ((lane >> 4) << 4);
    const uint32_t bRowOff = (uint32_t)((wn * 64 + (lane & 7) + ((lane & 16) >> 1)) * 80)
                             + ((lane & 8) << 1);

    float acc[2][8][4];
    #pragma unroll
    for (int f = 0; f < 2; f++)
        #pragma unroll
        for (int n = 0; n < 8; n++)
            #pragma unroll
            for (int q = 0; q < 4; q++) acc[f][n][q] = 0.f;

    load_stage(sb + OFF_STG,         tid, m0, n0, 0);
    CP_COMMIT();
    load_stage(sb + OFF_STG + STAGE, tid, m0, n0, 32);
    CP_COMMIT();

    uint4* zp = (uint4*)out;
    uint4 zv; zv.x = zv.y = zv.z = zv.w = 0u;
    const long zg = (long)blockIdx.x * 512 + tid;

    for (int kt = 0; kt < 32; kt++) {
        const int slot = kt % 3;
        const uint32_t stgA = sb + OFF_STG + slot * STAGE;
        const uint32_t stgB = stgA + B_OFF;

        if (kt < 31) { CP_WAIT1(); } else { CP_WAIT0(); }
        __syncthreads();

        if (kt < 30) {
            load_stage(sb + OFF_STG + ((kt + 2) % 3) * STAGE, tid, m0, n0, (kt + 2) * 32);
            CP_COMMIT();
        }

        #pragma unroll
        for (int sub = 0; sub < 2; sub++) {
            uint32_t ah[2][4], al[2][4];
            #pragma unroll
            for (int f = 0; f < 2; f++) {
                uint32_t aa = stgA + aRowOff + f * 1280 + sub * 32;
                LDSM4(ah[f], aa);
                LDSM4(al[f], aa + ALO);
            }
            #pragma unroll
            for (int np = 0; np < 4; np++) {
                uint32_t ba = stgB + bRowOff + np * 1280 + sub * 32;
                uint32_t bh[4], bl[4];
                LDSM4(bh, ba);
                LDSM4(bl, ba + BLO);
                #pragma unroll
                for (int f = 0; f < 2; f++) {
                    MMA16816(acc[f][2 * np],     ah[f], bh[0], bh[1]);
                    MMA16816(acc[f][2 * np],     ah[f], bl[0], bl[1]);
                    MMA16816(acc[f][2 * np],     al[f], bh[0], bh[1]);
                    MMA16816(acc[f][2 * np + 1], ah[f], bh[2], bh[3]);
                    MMA16816(acc[f][2 * np + 1], ah[f], bl[2], bl[3]);
                    MMA16816(acc[f][2 * np + 1], al[f], bh[2], bh[3]);
                }
            }
            #pragma unroll 3
            for (int j = 0; j < 6; j++)
                __stcs(zp + (long)(kt * 12 + sub * 6 + j) * 65536 + zg, zv);
        }
    }

    // ---------- epilogue ----------
    float* sPart = (float*)(smraw + OFF_STG);
    #pragma unroll
    for (int f = 0; f < 2; f++) {
        float le0[8] = {0,0,0,0,0,0,0,0};
        float le1[8] = {0,0,0,0,0,0,0,0};
        #pragma unroll
        for (int nf = 0; nf < 8; nf++) {
            int cb = wn * 64 + nf * 8 + tt * 2;
            float bv0 = sBias[cb], bv1 = sBias[cb + 1];
            float h00 = fmaxf(acc[f][nf][0] + bv0, 0.f);
            float h01 = fmaxf(acc[f][nf][1] + bv1, 0.f);
            float h10 = fmaxf(acc[f][nf][2] + bv0, 0.f);
            float h11 = fmaxf(acc[f][nf][3] + bv1, 0.f);
            const float* w0 = &sW2[cb * 8];
            const float* w1p = &sW2[(cb + 1) * 8];
            #pragma unroll
            for (int e = 0; e < 8; e++) {
                le0[e] += h00 * w0[e] + h01 * w1p[e];
                le1[e] += h10 * w0[e] + h11 * w1p[e];
            }
        }
        #pragma unroll
        for (int e = 0; e < 8; e++) {
            le0[e] += __shfl_xor_sync(0xffffffffu, le0[e], 1);
            le0[e] += __shfl_xor_sync(0xffffffffu, le0[e], 2);
            le1[e] += __shfl_xor_sync(0xffffffffu, le1[e], 1);
            le1[e] += __shfl_xor_sync(0xffffffffu, le1[e], 2);
        }
        if (tt == 0) {
            int r0 = wm * 32 + f * 16 + gg;
            float* p0 = &sPart[(wn * 128 + r0) * 8];
            *(float4*)p0       = make_float4(le0[0], le0[1], le0[2], le0[3]);
            *(float4*)(p0 + 4) = make_float4(le0[4], le0[5], le0[6], le0[7]);
            float* p1 = &sPart[(wn * 128 + r0 + 8) * 8];
            *(float4*)p1       = make_float4(le1[0], le1[1], le1[2], le1[3]);
            *(float4*)(p1 + 4) = make_float4(le1[4], le1[5], le1[6], le1[7]);
        }
    }
    __syncthreads();
    if (tid < 256) {
        int row = tid >> 1, e4 = (tid & 1) * 4;
        float4 v0 = *(float4*)&sPart[(0 * 128 + row) * 8 + e4];
        float4 v1 = *(float4*)&sPart[(1 * 128 + row) * 8 + e4];
        float4 v2 = *(float4*)&sPart[(2 * 128 + row) * 8 + e4];
        float4 v3 = *(float4*)&sPart[(3 * 128 + row) * 8 + e4];
        float4 v = make_float4(((v0.x + v1.x) + v2.x) + v3.x,
                               ((v0.y + v1.y) + v2.y) + v3.y,
                               ((v0.z + v1.z) + v2.z) + v3.z,
                               ((v0.w + v1.w) + v2.w) + v3.w);
        *(float4*)(g_plog + ((long)blockN * 4096 + m0 + row) * 8 + e4) = v;
    }
}

// ============ k_tail: softmax/top2 + counts, 32-block sync, positions + scatter + aux ============
__global__ void k_tail(const float* __restrict__ b2, float* __restrict__ out)
{
    __shared__ float wsum[4][8];
    __shared__ int scnt[8];
    __shared__ int sE[256];
    __shared__ float sP[256];
    __shared__ unsigned int wtot[8][4];
    __shared__ int base[8];

    const int b = blockIdx.x;
    const int tid = threadIdx.x;
    const int lane = tid & 31, warp = tid >> 5;

    if (tid < 8) scnt[tid] = 0;
    __syncthreads();

    if (tid < 128) {
        int tok = b * 128 + tid;
        int bb = tok >> 11;
        float l[8] = {0,0,0,0,0,0,0,0};
        #pragma unroll
        for (int q = 0; q < 4; q++) {
            const float4* p = (const float4*)(g_plog + ((long)q * 4096 + tok) * 8);
            float4 u = p[0], v = p[1];
            l[0] += u.x; l[1] += u.y; l[2] += u.z; l[3] += u.w;
            l[4] += v.x; l[5] += v.y; l[6] += v.z; l[7] += v.w;
        }
        float m = -1e30f;
        #pragma unroll
        for (int e = 0; e < 8; e++) {
            l[e] += b2[e] + g_adj[bb * 8 + e];
            m = fmaxf(m, l[e]);
        }
        float p[8], s = 0.f;
        #pragma unroll
        for (int e = 0; e < 8; e++) { p[e] = expf(l[e] - m); s += p[e]; }
        float inv = 1.f / s;
        #pragma unroll
        for (int e = 0; e < 8; e++) p[e] *= inv;
        {
            float* pr = out + PROBS_OFF + (long)tok * 8;
            *(float4*)pr       = make_float4(p[0], p[1], p[2], p[3]);
            *(float4*)(pr + 4) = make_float4(p[4], p[5], p[6], p[7]);
        }
        int e1 = 0;
        #pragma unroll
        for (int e = 1; e < 8; e++) if (p[e] > p[e1]) e1 = e;
        int e2 = (e1 == 0) ? 1 : 0;
        #pragma unroll
        for (int e = 0; e < 8; e++) if (e != e1 && p[e] > p[e2]) e2 = e;
        float d = p[e1] + p[e2] + 1e-8f;
        sE[tid * 2]     = e1;
        sE[tid * 2 + 1] = e2;
        sP[tid * 2]     = p[e1] / d;
        sP[tid * 2 + 1] = p[e2] / d;
        atomicAdd(&scnt[e1], 1);
        atomicAdd(&scnt[e2], 1);

        float w[8];
        #pragma unroll
        for (int e = 0; e < 8; e++) {
            float v = p[e];
            #pragma unroll
            for (int off = 16; off > 0; off >>= 1)
                v += __shfl_xor_sync(0xffffffffu, v, off);
            w[e] = v;
        }
        if (lane == 0) {
            #pragma unroll
            for (int e = 0; e < 8; e++) wsum[warp][e] = w[e];
        }
    }
    __syncthreads();
    if (tid < 8) {
        g_psum[b * 8 + tid] =
            ((wsum[0][tid] + wsum[1][tid]) + wsum[2][tid]) + wsum[3][tid];
        g_cnt[b * 8 + tid] = scnt[tid];
    }
    __threadfence();
    __syncthreads();

    if (tid == 0) {
        atomicAdd(&g_done, 1);
        while (atomicAdd(&g_done, 0) < 32) __nanosleep(64);
    }
    __syncthreads();
    __threadfence();

    if (tid < 8) {
        int s = 0;
        for (int q = 0; q < b; q++) s += g_cnt[q * 8 + tid];
        base[tid] = s;
    }

    const int e = sE[tid];
    const float pv = sP[tid];
    unsigned int c[4] = {0, 0, 0, 0};
    c[e >> 1] = 1u << ((e & 1) * 16);
    unsigned int inc[4] = {c[0], c[1], c[2], c[3]};
    #pragma unroll
    for (int off = 1; off < 32; off <<= 1) {
        #pragma unroll
        for (int w = 0; w < 4; w++) {
            unsigned int v = __shfl_up_sync(0xffffffffu, inc[w], off);
            if (lane >= off) inc[w] += v;
        }
    }
    if (lane == 31) {
        #pragma unroll
        for (int w = 0; w < 4; w++) wtot[warp][w] = inc[w];
    }
    __syncthreads();

    unsigned int exc = inc[e >> 1] - c[e >> 1];
    for (int q = 0; q < warp; q++) exc += wtot[q][e >> 1];
    int local = (int)((exc >> ((e & 1) * 16)) & 0xffffu);
    int pos = base[e] + local;

    if (pos < CAP) {
        long n = (long)b * 256 + tid;
        long tok = n >> 1;
        long o = tok * 12288L + (long)e * 1536L + pos;
        out[o] = 1.0f;
        out[DISP_ELEMS + o] = pv;
    }

    if (b == 0 && tid == 0) {
        float aux = 0.f;
        #pragma unroll
        for (int ee = 0; ee < 8; ee++) {
            float ps = 0.f; int ct = 0;
            for (int q = 0; q < 32; q++) {
                ps += g_psum[q * 8 + ee];
                ct += g_cnt[q * 8 + ee];
            }
            aux += (ps * (1.f / 4096.f)) * ((float)ct * (1.f / 8192.f));
        }
        out[AUX_OFF] = aux * 8.f;
    }

    if (tid == 0) {
        int v = atomicAdd(&g_done2, 1);
        if (v == 31) { g_done = 0; g_done2 = 0; }
    }
}

// ---------------- launch ----------------
extern "C" void kernel_launch(void* const* d_in, const int* in_sizes, int n_in,
                              void* d_out, int out_size)
{
    const float* hs    = (const float*)d_in[0];
    const float* w1    = (const float*)d_in[1];
    const float* b1    = (const float*)d_in[2];
    const float* w2    = (const float*)d_in[3];
    const float* b2    = (const float*)d_in[4];
    const float* wc1   = (const float*)d_in[5];
    const float* bc1   = (const float*)d_in[6];
    const float* wc2   = (const float*)d_in[7];
    const float* bc2   = (const float*)d_in[8];
    const float* cache = (const float*)d_in[9];
    float* out = (float*)d_out;

    cudaFuncSetAttribute(k_gemm, cudaFuncAttributeMaxDynamicSharedMemorySize, DYNSMEM);

    k_prep<<<640, 256>>>(hs, w1);
    k_gemm<<<130, 512, DYNSMEM>>>(b1, w2, wc1, bc1, wc2, bc2, cache, out);
    k_tail<<<32, 256>>>(b2, out);
}